// round 16
// baseline (speedup 1.0000x reference)
#include <cuda_runtime.h>
#include <math.h>

// Row-normalize: out[r, :] = in[r, :] * inv(sum(in[r, :])), inv->0 if non-finite.
// Row = 1024 f32 = 128 x 32B (v8) chunks. One warp per row; each lane owns
// 4 x 256-bit (v8.f32) loads/stores (sm_103a 256-bit global access).
// R16: v8 + .cs streaming hints combined. Four prior variants all pinned at
// 6.43-6.50 TB/s (path-independent LTS cap) — this is the roofline hold.

#define ROW_LEN 1024
#define V8_PER_LANE 4               // 32 lanes * 4 * 8 = 1024 floats per warp
#define WARPS_PER_BLOCK 8
#define THREADS_PER_BLOCK (WARPS_PER_BLOCK * 32)

__device__ __forceinline__ void ldg_v8_cs(const float* p, float* r) {
    asm volatile("ld.global.cs.v8.f32 {%0,%1,%2,%3,%4,%5,%6,%7}, [%8];"
                 : "=f"(r[0]), "=f"(r[1]), "=f"(r[2]), "=f"(r[3]),
                   "=f"(r[4]), "=f"(r[5]), "=f"(r[6]), "=f"(r[7])
                 : "l"(p));
}

__device__ __forceinline__ void stg_v8_cs(float* p, const float* r) {
    asm volatile("st.global.cs.v8.f32 [%0], {%1,%2,%3,%4,%5,%6,%7,%8};"
                 :: "l"(p),
                    "f"(r[0]), "f"(r[1]), "f"(r[2]), "f"(r[3]),
                    "f"(r[4]), "f"(r[5]), "f"(r[6]), "f"(r[7])
                 : "memory");
}

__global__ __launch_bounds__(THREADS_PER_BLOCK)
void normalizer_kernel(const float* __restrict__ in,
                       float* __restrict__ out,
                       int n_rows)
{
    const int warp_id = threadIdx.x >> 5;
    const int lane    = threadIdx.x & 31;
    const int row     = blockIdx.x * WARPS_PER_BLOCK + warp_id;
    if (row >= n_rows) return;

    const float* row_in  = in  + (size_t)row * ROW_LEN;
    float*       row_out = out + (size_t)row * ROW_LEN;

    // Front-batched 256-bit streaming loads: 4 independent LDG.256.CS per lane.
    float v[V8_PER_LANE][8];
#pragma unroll
    for (int k = 0; k < V8_PER_LANE; k++) {
        ldg_v8_cs(row_in + (size_t)(lane + k * 32) * 8, v[k]);
    }

    // Per-lane partial sum (balanced tree).
    float s = 0.0f;
#pragma unroll
    for (int k = 0; k < V8_PER_LANE; k++) {
        float t0 = (v[k][0] + v[k][1]) + (v[k][2] + v[k][3]);
        float t1 = (v[k][4] + v[k][5]) + (v[k][6] + v[k][7]);
        s += t0 + t1;
    }

    // Warp butterfly reduction -> all lanes hold the full row sum.
#pragma unroll
    for (int off = 16; off > 0; off >>= 1) {
        s += __shfl_xor_sync(0xFFFFFFFFu, s, off);
    }

    float inv = 1.0f / s;
    if (!isfinite(inv)) inv = 0.0f;

    // Scale in registers, 256-bit streaming stores.
#pragma unroll
    for (int k = 0; k < V8_PER_LANE; k++) {
        float o[8];
#pragma unroll
        for (int j = 0; j < 8; j++) o[j] = v[k][j] * inv;
        stg_v8_cs(row_out + (size_t)(lane + k * 32) * 8, o);
    }
}

extern "C" void kernel_launch(void* const* d_in, const int* in_sizes, int n_in,
                              void* d_out, int out_size)
{
    const float* in  = (const float*)d_in[0];
    float*       out = (float*)d_out;

    const int total  = in_sizes[0];          // 2*32*1024*1024 = 67108864
    const int n_rows = total / ROW_LEN;      // 65536

    const int blocks = (n_rows + WARPS_PER_BLOCK - 1) / WARPS_PER_BLOCK; // 8192
    normalizer_kernel<<<blocks, THREADS_PER_BLOCK>>>(in, out, n_rows);
}

// round 17
// speedup vs baseline: 1.0012x; 1.0012x over previous
#include <cuda_runtime.h>
#include <math.h>

// Row-normalize: out[r, :] = in[r, :] * inv(sum(in[r, :])), inv->0 if non-finite.
// Row = 1024 f32 = 128 x 32B (v8) chunks. One warp per row; each lane owns
// 4 x 256-bit (v8.f32) loads/stores (sm_103a 256-bit global access).
// R16: v8 + .cs streaming hints combined. Four prior variants all pinned at
// 6.43-6.50 TB/s (path-independent LTS cap) — this is the roofline hold.

#define ROW_LEN 1024
#define V8_PER_LANE 4               // 32 lanes * 4 * 8 = 1024 floats per warp
#define WARPS_PER_BLOCK 8
#define THREADS_PER_BLOCK (WARPS_PER_BLOCK * 32)

__device__ __forceinline__ void ldg_v8_cs(const float* p, float* r) {
    asm volatile("ld.global.cs.v8.f32 {%0,%1,%2,%3,%4,%5,%6,%7}, [%8];"
                 : "=f"(r[0]), "=f"(r[1]), "=f"(r[2]), "=f"(r[3]),
                   "=f"(r[4]), "=f"(r[5]), "=f"(r[6]), "=f"(r[7])
                 : "l"(p));
}

__device__ __forceinline__ void stg_v8_cs(float* p, const float* r) {
    asm volatile("st.global.cs.v8.f32 [%0], {%1,%2,%3,%4,%5,%6,%7,%8};"
                 :: "l"(p),
                    "f"(r[0]), "f"(r[1]), "f"(r[2]), "f"(r[3]),
                    "f"(r[4]), "f"(r[5]), "f"(r[6]), "f"(r[7])
                 : "memory");
}

__global__ __launch_bounds__(THREADS_PER_BLOCK)
void normalizer_kernel(const float* __restrict__ in,
                       float* __restrict__ out,
                       int n_rows)
{
    const int warp_id = threadIdx.x >> 5;
    const int lane    = threadIdx.x & 31;
    const int row     = blockIdx.x * WARPS_PER_BLOCK + warp_id;
    if (row >= n_rows) return;

    const float* row_in  = in  + (size_t)row * ROW_LEN;
    float*       row_out = out + (size_t)row * ROW_LEN;

    // Front-batched 256-bit streaming loads: 4 independent LDG.256.CS per lane.
    float v[V8_PER_LANE][8];
#pragma unroll
    for (int k = 0; k < V8_PER_LANE; k++) {
        ldg_v8_cs(row_in + (size_t)(lane + k * 32) * 8, v[k]);
    }

    // Per-lane partial sum (balanced tree).
    float s = 0.0f;
#pragma unroll
    for (int k = 0; k < V8_PER_LANE; k++) {
        float t0 = (v[k][0] + v[k][1]) + (v[k][2] + v[k][3]);
        float t1 = (v[k][4] + v[k][5]) + (v[k][6] + v[k][7]);
        s += t0 + t1;
    }

    // Warp butterfly reduction -> all lanes hold the full row sum.
#pragma unroll
    for (int off = 16; off > 0; off >>= 1) {
        s += __shfl_xor_sync(0xFFFFFFFFu, s, off);
    }

    float inv = 1.0f / s;
    if (!isfinite(inv)) inv = 0.0f;

    // Scale in registers, 256-bit streaming stores.
#pragma unroll
    for (int k = 0; k < V8_PER_LANE; k++) {
        float o[8];
#pragma unroll
        for (int j = 0; j < 8; j++) o[j] = v[k][j] * inv;
        stg_v8_cs(row_out + (size_t)(lane + k * 32) * 8, o);
    }
}

extern "C" void kernel_launch(void* const* d_in, const int* in_sizes, int n_in,
                              void* d_out, int out_size)
{
    const float* in  = (const float*)d_in[0];
    float*       out = (float*)d_out;

    const int total  = in_sizes[0];          // 2*32*1024*1024 = 67108864
    const int n_rows = total / ROW_LEN;      // 65536

    const int blocks = (n_rows + WARPS_PER_BLOCK - 1) / WARPS_PER_BLOCK; // 8192
    normalizer_kernel<<<blocks, THREADS_PER_BLOCK>>>(in, out, n_rows);
}